// round 1
// baseline (speedup 1.0000x reference)
#include <cuda_runtime.h>

// Problem constants (fixed shapes for this problem)
#define NN   65536      // total nodes
#define PP   1024       // nodes per graph
#define BB   64         // graphs
#define HH   32         // hidden dim
#define DIN  16         // input feature dim

// Scratch (device globals; no allocation allowed)
__device__ __align__(16) float d_deg[NN];
__device__ __align__(16) float d_G  [NN * HH];   // g = h * dis  (message payload)
__device__ __align__(16) float d_ACC[NN * HH];   // accumulator (init = g -> self loop)
__device__ __align__(16) float d_pool[BB * HH];  // per-graph pooled features

__device__ __forceinline__ void red_add_v4(float* a, float4 v) {
    asm volatile("red.global.add.v4.f32 [%0], {%1,%2,%3,%4};"
                 :: "l"(a), "f"(v.x), "f"(v.y), "f"(v.z), "f"(v.w) : "memory");
}

// K0: deg = 1 (self loop), pool = 0
__global__ void k_init(int n) {
    int i = blockIdx.x * blockDim.x + threadIdx.x;
    if (i < n) d_deg[i] = 1.0f;
    if (i < BB * HH) d_pool[i] = 0.0f;
}

// K1: deg[dst] += 1 per edge
__global__ void k_deg(const int* __restrict__ dst, int e) {
    int i = blockIdx.x * blockDim.x + threadIdx.x;
    if (i < e) atomicAdd(&d_deg[dst[i]], 1.0f);
}

// K2: g = (x @ W1^T) * dis ; ACC = g (self-loop contribution)
__global__ void k_pre1(const float* __restrict__ x, const float* __restrict__ W1, int n) {
    __shared__ float sW[HH * DIN];
    for (int i = threadIdx.x; i < HH * DIN; i += blockDim.x) sW[i] = W1[i];
    __syncthreads();
    int nd = blockIdx.x * blockDim.x + threadIdx.x;
    if (nd >= n) return;
    float xv[DIN];
    const float4* xp = (const float4*)(x + (size_t)nd * DIN);
#pragma unroll
    for (int i = 0; i < DIN / 4; i++) {
        float4 t = xp[i];
        xv[4*i] = t.x; xv[4*i+1] = t.y; xv[4*i+2] = t.z; xv[4*i+3] = t.w;
    }
    float dis = rsqrtf(d_deg[nd]);
    float h[HH];
#pragma unroll
    for (int j = 0; j < HH; j++) {
        float a = 0.f;
#pragma unroll
        for (int i = 0; i < DIN; i++) a = fmaf(xv[i], sW[j * DIN + i], a);
        h[j] = a * dis;
    }
    float4* gp = (float4*)(d_G + (size_t)nd * HH);
    float4* ap = (float4*)(d_ACC + (size_t)nd * HH);
#pragma unroll
    for (int i = 0; i < HH / 4; i++) {
        float4 v = make_float4(h[4*i], h[4*i+1], h[4*i+2], h[4*i+3]);
        gp[i] = v; ap[i] = v;
    }
}

// K3/K5: scatter ACC[dst] += G[src], 8 threads per edge, 16B vector RED each
__global__ void k_scatter(const int* __restrict__ src, const int* __restrict__ dst, int e) {
    int t = blockIdx.x * blockDim.x + threadIdx.x;
    int ed = t >> 3, q = t & 7;
    if (ed >= e) return;
    int s = src[ed], d = dst[ed];
    float4 v = ((const float4*)d_G)[(size_t)s * 8 + q];
    red_add_v4(&d_ACC[(size_t)d * HH + q * 4], v);
}

// K4: t = tanh(dis*ACC + b1); g2 = (t @ W2^T) * dis ; G = ACC = g2
__global__ void k_mid(const float* __restrict__ b1, const float* __restrict__ W2, int n) {
    __shared__ float sW[HH * HH];
    __shared__ float sb[HH];
    for (int i = threadIdx.x; i < HH * HH; i += blockDim.x) sW[i] = W2[i];
    if (threadIdx.x < HH) sb[threadIdx.x] = b1[threadIdx.x];
    __syncthreads();
    int nd = blockIdx.x * blockDim.x + threadIdx.x;
    if (nd >= n) return;
    float dis = rsqrtf(d_deg[nd]);
    float t[HH];
    const float4* ap = (const float4*)(d_ACC + (size_t)nd * HH);
#pragma unroll
    for (int i = 0; i < HH / 4; i++) {
        float4 v = ap[i];
        t[4*i]   = tanhf(fmaf(dis, v.x, sb[4*i]));
        t[4*i+1] = tanhf(fmaf(dis, v.y, sb[4*i+1]));
        t[4*i+2] = tanhf(fmaf(dis, v.z, sb[4*i+2]));
        t[4*i+3] = tanhf(fmaf(dis, v.w, sb[4*i+3]));
    }
    float g[HH];
#pragma unroll
    for (int j = 0; j < HH; j++) {
        float a = 0.f;
#pragma unroll
        for (int k = 0; k < HH; k++) a = fmaf(t[k], sW[j * HH + k], a);
        g[j] = a * dis;
    }
    float4* gp = (float4*)(d_G + (size_t)nd * HH);
    float4* wp = (float4*)(d_ACC + (size_t)nd * HH);
#pragma unroll
    for (int i = 0; i < HH / 4; i++) {
        float4 v = make_float4(g[4*i], g[4*i+1], g[4*i+2], g[4*i+3]);
        gp[i] = v; wp[i] = v;
    }
}

// K6: u = tanh(dis*ACC + b2); v = tanh(u @ Wl^T + bl); pool[graph] += v (block reduce)
__global__ void k_post(const float* __restrict__ b2, const float* __restrict__ Wl,
                       const float* __restrict__ bl, int n) {
    __shared__ float sW[HH * HH];
    __shared__ float sb2[HH];
    __shared__ float sbl[HH];
    __shared__ float red[256][HH + 1];
    for (int i = threadIdx.x; i < HH * HH; i += blockDim.x) sW[i] = Wl[i];
    if (threadIdx.x < HH) { sb2[threadIdx.x] = b2[threadIdx.x]; sbl[threadIdx.x] = bl[threadIdx.x]; }
    __syncthreads();
    int nd = blockIdx.x * blockDim.x + threadIdx.x;
    if (nd >= n) return;
    float dis = rsqrtf(d_deg[nd]);
    float u[HH];
    const float4* ap = (const float4*)(d_ACC + (size_t)nd * HH);
#pragma unroll
    for (int i = 0; i < HH / 4; i++) {
        float4 v = ap[i];
        u[4*i]   = tanhf(fmaf(dis, v.x, sb2[4*i]));
        u[4*i+1] = tanhf(fmaf(dis, v.y, sb2[4*i+1]));
        u[4*i+2] = tanhf(fmaf(dis, v.z, sb2[4*i+2]));
        u[4*i+3] = tanhf(fmaf(dis, v.w, sb2[4*i+3]));
    }
#pragma unroll
    for (int j = 0; j < HH; j++) {
        float a = sbl[j];
#pragma unroll
        for (int k = 0; k < HH; k++) a = fmaf(u[k], sW[j * HH + k], a);
        red[threadIdx.x][j] = tanhf(a);
    }
    __syncthreads();
    // block covers 256 consecutive nodes -> single graph: g = blockIdx.x/4
    int g = blockIdx.x >> 2;
    if (threadIdx.x < HH) {
        float s = 0.f;
#pragma unroll 8
        for (int r = 0; r < 256; r++) s += red[r][threadIdx.x];
        atomicAdd(&d_pool[g * HH + threadIdx.x], s);
    }
}

// K7: heads — one thread per batch row
__global__ void k_head(const float* __restrict__ share,
                       const float* __restrict__ Wp, const float* __restrict__ bp,
                       const float* __restrict__ Vw1, const float* __restrict__ Vb1,
                       const float* __restrict__ Vw2, const float* __restrict__ Vb2,
                       const float* __restrict__ Vw3, const float* __restrict__ Vb3,
                       const float* __restrict__ Cw1, const float* __restrict__ Cb1,
                       const float* __restrict__ Cw2, const float* __restrict__ Cb2,
                       float* __restrict__ out) {
    int b = threadIdx.x;
    if (b >= BB) return;
    float p[HH];
#pragma unroll
    for (int k = 0; k < HH; k++) p[k] = d_pool[b * HH + k];
    float h1[HH];
#pragma unroll
    for (int j = 0; j < HH; j++) {
        float a = bp[j];
#pragma unroll
        for (int k = 0; k < HH; k++) a = fmaf(p[k], Wp[j * HH + k], a);
        h1[j] = a;   // no tanh on Wp output
    }
    float s[2 * HH];
#pragma unroll
    for (int k = 0; k < 2 * HH; k++) s[k] = share[b * 2 * HH + k];
    float a1[HH];
#pragma unroll
    for (int j = 0; j < HH; j++) {
        float a = Vb1[j];
#pragma unroll
        for (int k = 0; k < 2 * HH; k++) a = fmaf(s[k], Vw1[j * 2 * HH + k], a);
        a1[j] = tanhf(a);
    }
    float a2[HH];
#pragma unroll
    for (int j = 0; j < HH; j++) {
        float a = Vb2[j];
#pragma unroll
        for (int k = 0; k < HH; k++) a = fmaf(a1[k], Vw2[j * HH + k], a);
        a2[j] = tanhf(a);
    }
    float h2[HH];
#pragma unroll
    for (int j = 0; j < HH; j++) {
        float a = Vb3[j];
#pragma unroll
        for (int k = 0; k < HH; k++) a = fmaf(a2[k], Vw3[j * HH + k], a);
        h2[j] = a;   // linear (no tanh)
    }
    float val = Cb2[0];
#pragma unroll
    for (int j = 0; j < HH; j++) {
        float a = Cb1[j];
#pragma unroll
        for (int k = 0; k < HH; k++) a = fmaf(h1[k], Cw1[j * 2 * HH + k], a);
#pragma unroll
        for (int k = 0; k < HH; k++) a = fmaf(h2[k], Cw1[j * 2 * HH + HH + k], a);
        val = fmaf(tanhf(a), Cw2[j], val);
    }
    out[b] = val;
}

extern "C" void kernel_launch(void* const* d_in, const int* in_sizes, int n_in,
                              void* d_out, int out_size) {
    const float* x     = (const float*)d_in[0];
    const int*   ei    = (const int*)  d_in[1];
    // d_in[2] = value_batch (node // 1024, recomputed on device)
    const float* share = (const float*)d_in[3];
    const float* W1  = (const float*)d_in[4];
    const float* b1  = (const float*)d_in[5];
    const float* W2  = (const float*)d_in[6];
    const float* b2  = (const float*)d_in[7];
    const float* Wl  = (const float*)d_in[8];
    const float* bl  = (const float*)d_in[9];
    const float* Wp  = (const float*)d_in[10];
    const float* bp  = (const float*)d_in[11];
    const float* Vw1 = (const float*)d_in[12];
    const float* Vb1 = (const float*)d_in[13];
    const float* Vw2 = (const float*)d_in[14];
    const float* Vb2 = (const float*)d_in[15];
    const float* Vw3 = (const float*)d_in[16];
    const float* Vb3 = (const float*)d_in[17];
    const float* Cw1 = (const float*)d_in[18];
    const float* Cb1 = (const float*)d_in[19];
    const float* Cw2 = (const float*)d_in[20];
    const float* Cb2 = (const float*)d_in[21];

    int n = in_sizes[0] / DIN;          // 65536
    int e = in_sizes[1] / 2;            // 2097152
    const int* src = ei;
    const int* dst = ei + e;

    int nb  = (n + 255) / 256;
    int eb  = (e + 255) / 256;
    long long sw = (long long)e * 8;
    int sb  = (int)((sw + 255) / 256);

    k_init   <<<nb, 256>>>(n);
    k_deg    <<<eb, 256>>>(dst, e);
    k_pre1   <<<nb, 256>>>(x, W1, n);
    k_scatter<<<sb, 256>>>(src, dst, e);
    k_mid    <<<nb, 256>>>(b1, W2, n);
    k_scatter<<<sb, 256>>>(src, dst, e);
    k_post   <<<nb, 256>>>(b2, Wl, bl, n);
    k_head   <<<1, 64>>>(share, Wp, bp, Vw1, Vb1, Vw2, Vb2, Vw3, Vb3,
                         Cw1, Cb1, Cw2, Cb2, (float*)d_out);
}